// round 7
// baseline (speedup 1.0000x reference)
#include <cuda_runtime.h>
#include <cuda_bf16.h>
#include <math.h>
#include <stdint.h>

#define BB 2
#define SS 2048
#define DD 2048
#define HH 16
#define QPd 1024
#define KVPd 1365
#define CKVN 1429
#define FFd 8192
#define MMr 4096
#define KVL_PAD 1376
#define WDKV_PAD 1440

__device__ float g_h[(size_t)MMr * DD];
__device__ float g_cq[(size_t)MMr * QPd];
__device__ float g_qraw[(size_t)MMr * DD];
__device__ float g_kvlora[(size_t)MMr * KVL_PAD];
__device__ float g_kvraw[(size_t)MMr * 3072];
__device__ float g_q[(size_t)MMr * DD];
__device__ float g_k[(size_t)MMr * DD];
__device__ float g_v[(size_t)MMr * DD];
__device__ float g_o[(size_t)MMr * DD];
__device__ float g_x2[(size_t)MMr * DD];
__device__ float g_ff1[(size_t)MMr * FFd];
__device__ float g_woT[(size_t)DD * DD];
__device__ float g_wdkvp[(size_t)DD * WDKV_PAD];
__device__ float g_freqs[32];

__device__ __forceinline__ uint32_t f2tf(float x) {
    uint32_t u;
    asm("cvt.rna.tf32.f32 %0, %1;" : "=r"(u) : "f"(x));
    return u;
}
__device__ __forceinline__ void mma_tf32(float* c, const uint32_t* a, uint32_t b0, uint32_t b1) {
    asm volatile(
        "mma.sync.aligned.m16n8k8.row.col.f32.tf32.tf32.f32 "
        "{%0,%1,%2,%3}, {%4,%5,%6,%7}, {%8,%9}, {%0,%1,%2,%3};"
        : "+f"(c[0]), "+f"(c[1]), "+f"(c[2]), "+f"(c[3])
        : "r"(a[0]), "r"(a[1]), "r"(a[2]), "r"(a[3]), "r"(b0), "r"(b1));
}
__device__ __forceinline__ void cp16(float* dst, const float* src, const float* safe, bool p) {
    uint32_t d = (uint32_t)__cvta_generic_to_shared(dst);
    const float* s = p ? src : safe;
    int sz = p ? 16 : 0;
    asm volatile("cp.async.cg.shared.global [%0], [%1], 16, %2;" :: "r"(d), "l"(s), "r"(sz));
}

#define BM 128
#define BN 128
#define BKt 32
#define ASTR 36
#define BSTR 132
#define AS_ELE (BM * ASTR)
#define BS_ELE (BKt * BSTR)
#define GEMM_SMEM (2 * (AS_ELE + BS_ELE) * 4)

// EPI: 0 none, 1 bias+GELU, 2 (+bias)+residual
template <int EPI>
__global__ __launch_bounds__(256) void gemm_kernel(
    const float* __restrict__ A, int lda, int kbuf,
    const float* __restrict__ B, int ldb, int nbuf,
    float* __restrict__ C, int ldc, int M, int N, int K,
    const float* __restrict__ bias, const float* __restrict__ res, int ldres)
{
    extern __shared__ float smemb[];
    float* As = smemb;
    float* Bs = smemb + 2 * AS_ELE;
    const int tid = threadIdx.x, lane = tid & 31, warp = tid >> 5;
    const int wm = warp >> 1, wn = warp & 1;
    const int bm0 = blockIdx.y * BM, bn0 = blockIdx.x * BN;

    float acc[2][8][4];
#pragma unroll
    for (int i = 0; i < 2; i++)
#pragma unroll
        for (int j = 0; j < 8; j++)
#pragma unroll
            for (int c = 0; c < 4; c++) acc[i][j][c] = 0.f;

    const int KT = (K + BKt - 1) / BKt;
    auto load_tiles = [&](int buf, int k0) {
        float* Ab = As + buf * AS_ELE;
        float* Bb = Bs + buf * BS_ELE;
        const int ar = tid >> 3, ac = (tid & 7) * 4;
#pragma unroll
        for (int i = 0; i < 4; i++) {
            int r = i * 32 + ar;
            cp16(Ab + r * ASTR + ac, A + (size_t)(bm0 + r) * lda + k0 + ac, A, (k0 + ac) < kbuf);
        }
        const int br = tid >> 5, bc = (tid & 31) * 4;
#pragma unroll
        for (int i = 0; i < 4; i++) {
            int r = i * 8 + br;
            cp16(Bb + r * BSTR + bc, B + (size_t)(k0 + r) * ldb + bn0 + bc, B,
                 ((k0 + r) < K) && ((bn0 + bc) < nbuf));
        }
        asm volatile("cp.async.commit_group;");
    };

    load_tiles(0, 0);
    int buf = 0;
    for (int kt = 0; kt < KT; kt++) {
        if (kt + 1 < KT) {
            load_tiles(buf ^ 1, (kt + 1) * BKt);
            asm volatile("cp.async.wait_group 1;");
        } else {
            asm volatile("cp.async.wait_group 0;");
        }
        __syncthreads();
        const float* Ab = As + buf * AS_ELE;
        const float* Bb = Bs + buf * BS_ELE;
#pragma unroll
        for (int ks = 0; ks < BKt / 8; ks++) {
            const int kb = ks * 8;
            uint32_t a[2][4];
#pragma unroll
            for (int im = 0; im < 2; im++) {
                const int r = wm * 32 + im * 16 + (lane >> 2);
                const int cc = kb + (lane & 3);
                a[im][0] = f2tf(Ab[r * ASTR + cc]);
                a[im][1] = f2tf(Ab[(r + 8) * ASTR + cc]);
                a[im][2] = f2tf(Ab[r * ASTR + cc + 4]);
                a[im][3] = f2tf(Ab[(r + 8) * ASTR + cc + 4]);
            }
#pragma unroll
            for (int in_ = 0; in_ < 8; in_++) {
                const int c = wn * 64 + in_ * 8 + (lane >> 2);
                uint32_t b0 = f2tf(Bb[(kb + (lane & 3)) * BSTR + c]);
                uint32_t b1 = f2tf(Bb[(kb + (lane & 3) + 4) * BSTR + c]);
#pragma unroll
                for (int im = 0; im < 2; im++) mma_tf32(acc[im][in_], a[im], b0, b1);
            }
        }
        __syncthreads();
        buf ^= 1;
    }
#pragma unroll
    for (int im = 0; im < 2; im++)
#pragma unroll
        for (int in_ = 0; in_ < 8; in_++) {
            const int r0 = bm0 + wm * 32 + im * 16 + (lane >> 2);
            const int c0 = bn0 + wn * 64 + in_ * 8 + 2 * (lane & 3);
#pragma unroll
            for (int cc = 0; cc < 4; cc++) {
                int r = r0 + (cc >> 1) * 8;
                int c = c0 + (cc & 1);
                if (c < N) {
                    float v = acc[im][in_][cc];
                    if (EPI == 1) {
                        v += bias[c];
                        v = 0.5f * v * (1.f + erff(v * 0.7071067811865475f));
                    } else if (EPI == 2) {
                        if (bias) v += bias[c];
                        v += res[(size_t)r * ldres + c];
                    }
                    C[(size_t)r * ldc + c] = v;
                }
            }
        }
}

__global__ void ln_kernel(const float* __restrict__ in, int ldin, int cols,
                          const float* __restrict__ w, const float* __restrict__ b,
                          float* __restrict__ out, int ldout, int padto)
{
    extern __shared__ float sbuf[];
    __shared__ float red[8];
    __shared__ float bc[2];
    const int row = blockIdx.x, tid = threadIdx.x, lane = tid & 31, warp = tid >> 5;
    const float* ip = in + (size_t)row * ldin;
    float s = 0.f;
    for (int c = tid; c < cols; c += 256) { float v = ip[c]; sbuf[c] = v; s += v; }
#pragma unroll
    for (int o = 16; o > 0; o >>= 1) s += __shfl_xor_sync(0xffffffffu, s, o);
    if (lane == 0) red[warp] = s;
    __syncthreads();
    if (tid == 0) { float t = 0; for (int i = 0; i < 8; i++) t += red[i]; bc[0] = t / cols; }
    __syncthreads();
    float mean = bc[0], vs = 0.f;
    for (int c = tid; c < cols; c += 256) { float d = sbuf[c] - mean; vs += d * d; }
#pragma unroll
    for (int o = 16; o > 0; o >>= 1) vs += __shfl_xor_sync(0xffffffffu, vs, o);
    if (lane == 0) red[warp] = vs;
    __syncthreads();
    if (tid == 0) { float t = 0; for (int i = 0; i < 8; i++) t += red[i]; bc[1] = rsqrtf(t / cols + 1e-5f); }
    __syncthreads();
    float inv = bc[1];
    float* op = out + (size_t)row * ldout;
    for (int c = tid; c < cols; c += 256) op[c] = (sbuf[c] - mean) * inv * w[c] + b[c];
    for (int c = cols + tid; c < padto; c += 256) op[c] = 0.f;
}

__global__ void freqs_kernel() {
    int j = threadIdx.x;
    if (j < 32) g_freqs[j] = (float)exp(-(double)j * 0.14391156831212787);
}

__global__ void transpose_kernel(const float* __restrict__ in, float* __restrict__ out, int n) {
    __shared__ float t[32][33];
    int x = blockIdx.x * 32 + threadIdx.x;
    int y = blockIdx.y * 32 + threadIdx.y;
#pragma unroll
    for (int i = 0; i < 32; i += 8) t[threadIdx.y + i][threadIdx.x] = in[(size_t)(y + i) * n + x];
    __syncthreads();
    int ox = blockIdx.y * 32 + threadIdx.x;
    int oy = blockIdx.x * 32 + threadIdx.y;
#pragma unroll
    for (int i = 0; i < 32; i += 8) out[(size_t)(oy + i) * n + ox] = t[threadIdx.x][threadIdx.y + i];
}

__global__ void pad_wdkv_kernel(const float* __restrict__ in, float* __restrict__ out) {
    int r = blockIdx.x;
    for (int c = threadIdx.x; c < WDKV_PAD; c += 256)
        out[(size_t)r * WDKV_PAD + c] = (c < CKVN) ? in[(size_t)r * CKVN + c] : 0.f;
}

__global__ void rope_q_kernel(const float* __restrict__ qraw, float* __restrict__ qout) {
    int bs = blockIdx.x;
    int s = bs & (SS - 1), b = bs >> 11;
    for (int i = threadIdx.x; i < DD; i += 256) {
        int hh = i >> 7, d = i & 127;
        const float* src = qraw + (size_t)bs * DD + hh * 128;
        float v;
        if (d < 64) {
            v = src[d];
        } else {
            int dd = d - 64;
            int j = dd & 31;
            float t = (float)s * g_freqs[j];
            float x = src[64 + dd];
            float rx = (dd < 32) ? -src[64 + dd + 32] : src[64 + dd - 32];
            v = x * cosf(t) + rx * sinf(t);
        }
        qout[(((size_t)b * HH + hh) * SS + s) * 128 + d] = v;
    }
}

__global__ void reorder_kv_kernel(const float* __restrict__ kvraw, const float* __restrict__ ckv,
                                  float* __restrict__ kout, float* __restrict__ vout) {
    __shared__ float kr[64];
    int bs = blockIdx.x;
    int s = bs & (SS - 1), b = bs >> 11;
    int tid = threadIdx.x;
    if (tid < 64) {
        int dd = tid, j = dd & 31;
        float t = (float)s * g_freqs[j];
        const float* src = ckv + (size_t)bs * CKVN + KVPd;
        float x = src[dd];
        float rx = (dd < 32) ? -src[dd + 32] : src[dd - 32];
        kr[dd] = x * cosf(t) + rx * sinf(t);
    }
    __syncthreads();
    for (int i = tid; i < HH * 192; i += 256) {
        int hh = i / 192, d = i % 192;
        float v = kvraw[(size_t)bs * 3072 + i];
        size_t base = (((size_t)b * HH + hh) * SS + s) * 128;
        if (d < 64) kout[base + d] = v;
        else vout[base + (d - 64)] = v;
    }
    for (int i = tid; i < HH * 64; i += 256) {
        int hh = i >> 6, dd = i & 63;
        kout[(((size_t)b * HH + hh) * SS + s) * 128 + 64 + dd] = kr[dd];
    }
}

#define ATTN_SMEM ((64 * 132 + 32 * 132 + 32 * 132 + 4 * 16 * 36) * 4)

__global__ __launch_bounds__(128) void attn_kernel(
    const float* __restrict__ Q, const float* __restrict__ Kk,
    const float* __restrict__ V, float* __restrict__ O)
{
    extern __shared__ float smema[];
    float* qs = smema;
    float* ks = qs + 64 * 132;
    float* vs = ks + 32 * 132;
    float* ps = vs + 32 * 132;
    const int qb = blockIdx.x, bh = blockIdx.y;
    const int b = bh >> 4, h = bh & 15;
    const int tid = threadIdx.x, lane = tid & 31, w = tid >> 5;
    const int g = lane >> 2, t = lane & 3;

    const float* Qb = Q + ((size_t)bh * SS + qb * 64) * 128;
    const float* Kb = Kk + (size_t)bh * SS * 128;
    const float* Vb = V + (size_t)bh * SS * 128;

    for (int i = tid; i < 64 * 32; i += 128) {
        int r = i >> 5, c4 = (i & 31) * 4;
        *(float4*)(qs + r * 132 + c4) = *(const float4*)(Qb + r * 128 + c4);
    }
    __syncthreads();

    float m_[2] = {-1e30f, -1e30f};
    float l_[2] = {0.f, 0.f};
    float o[16][4];
#pragma unroll
    for (int i = 0; i < 16; i++)
#pragma unroll
        for (int c = 0; c < 4; c++) o[i][c] = 0.f;

    const int nkt = qb * 2 + 2;
    const float scale = 0.08838834764831845f;
    float* pw = ps + w * 16 * 36;

    for (int kt = 0; kt < nkt; kt++) {
        for (int i = tid; i < 32 * 32; i += 128) {
            int r = i >> 5, c4 = (i & 31) * 4;
            *(float4*)(ks + r * 132 + c4) = *(const float4*)(Kb + ((size_t)kt * 32 + r) * 128 + c4);
            *(float4*)(vs + r * 132 + c4) = *(const float4*)(Vb + ((size_t)kt * 32 + r) * 128 + c4);
        }
        __syncthreads();

        float s[4][4];
#pragma unroll
        for (int nt = 0; nt < 4; nt++)
#pragma unroll
            for (int c = 0; c < 4; c++) s[nt][c] = 0.f;

#pragma unroll
        for (int k8 = 0; k8 < 16; k8++) {
            const int kb2 = k8 * 8;
            uint32_t a[4];
            const int rb = w * 16;
            a[0] = f2tf(qs[(rb + g) * 132 + kb2 + t]);
            a[1] = f2tf(qs[(rb + g + 8) * 132 + kb2 + t]);
            a[2] = f2tf(qs[(rb + g) * 132 + kb2 + t + 4]);
            a[3] = f2tf(qs[(rb + g + 8) * 132 + kb2 + t + 4]);
#pragma unroll
            for (int nt = 0; nt < 4; nt++) {
                uint32_t b0 = f2tf(ks[(nt * 8 + g) * 132 + kb2 + t]);
                uint32_t b1 = f2tf(ks[(nt * 8 + g) * 132 + kb2 + t + 4]);
                mma_tf32(s[nt], a, b0, b1);
            }
        }

        const int qrow0 = qb * 64 + w * 16 + g;
        const int qrow1 = qrow0 + 8;
#pragma unroll
        for (int nt = 0; nt < 4; nt++)
#pragma unroll
            for (int c = 0; c < 4; c++) {
                int row = (c < 2) ? qrow0 : qrow1;
                int kidx = kt * 32 + nt * 8 + 2 * t + (c & 1);
                float v = s[nt][c] * scale;
                if (kidx > row) v = -1e30f;
                s[nt][c] = v;
            }

        float mx0 = -1e30f, mx1 = -1e30f;
#pragma unroll
        for (int nt = 0; nt < 4; nt++) {
            mx0 = fmaxf(mx0, fmaxf(s[nt][0], s[nt][1]));
            mx1 = fmaxf(mx1, fmaxf(s[nt][2], s[nt][3]));
        }
#pragma unroll
        for (int off = 1; off < 4; off <<= 1) {
            mx0 = fmaxf(mx0, __shfl_xor_sync(0xffffffffu, mx0, off));
            mx1 = fmaxf(mx1, __shfl_xor_sync(0xffffffffu, mx1, off));
        }
        float mn0 = fmaxf(m_[0], mx0), mn1 = fmaxf(m_[1], mx1);
        float al0 = expf(m_[0] - mn0), al1 = expf(m_[1] - mn1);
        float rs0 = 0.f, rs1 = 0.f;
#pragma unroll
        for (int nt = 0; nt < 4; nt++) {
            s[nt][0] = expf(s[nt][0] - mn0);
            s[nt][1] = expf(s[nt][1] - mn0);
            s[nt][2] = expf(s[nt][2] - mn1);
            s[nt][3] = expf(s[nt][3] - mn1);
            rs0 += s[nt][0] + s[nt][1];
            rs1 += s[nt][2] + s[nt][3];
        }
#pragma unroll
        for (int off = 1; off < 4; off <<= 1) {
            rs0 += __shfl_xor_sync(0xffffffffu, rs0, off);
            rs1 += __shfl_xor_sync(0xffffffffu, rs1, off);
        }
        l_[0] = l_[0] * al0 + rs0;
        l_[1] = l_[1] * al1 + rs1;
        m_[0] = mn0; m_[1] = mn1;
#pragma unroll
        for (int nt = 0; nt < 16; nt++) {
            o[nt][0] *= al0; o[nt][1] *= al0;
            o[nt][2] *= al1; o[nt][3] *= al1;
        }

#pragma unroll
        for (int nt = 0; nt < 4; nt++) {
            pw[g * 36 + nt * 8 + 2 * t] = s[nt][0];
            pw[g * 36 + nt * 8 + 2 * t + 1] = s[nt][1];
            pw[(g + 8) * 36 + nt * 8 + 2 * t] = s[nt][2];
            pw[(g + 8) * 36 + nt * 8 + 2 * t + 1] = s[nt][3];
        }
        __syncwarp();

#pragma unroll
        for (int k8 = 0; k8 < 4; k8++) {
            const int kb2 = k8 * 8;
            uint32_t a[4];
            a[0] = f2tf(pw[g * 36 + kb2 + t]);
            a[1] = f2tf(pw[(g + 8) * 36 + kb2 + t]);
            a[2] = f2tf(pw[g * 36 + kb2 + t + 4]);
            a[3] = f2tf(pw[(g + 8) * 36 + kb2 + t + 4]);
#pragma unroll
            for (int nt = 0; nt < 16; nt++) {
                uint32_t b0 = f2tf(vs[(kb2 + t) * 132 + nt * 8 + g]);
                uint32_t b1 = f2tf(vs[(kb2 + t + 4) * 132 + nt * 8 + g]);
                mma_tf32(o[nt], a, b0, b1);
            }
        }
        __syncwarp();
        __syncthreads();
    }

    float inv0 = 1.f / l_[0], inv1 = 1.f / l_[1];
    const size_t gr0 = (size_t)b * SS + qb * 64 + w * 16 + g;
#pragma unroll
    for (int nt = 0; nt < 16; nt++) {
        int col = h * 128 + nt * 8 + 2 * t;
        O[gr0 * DD + col] = o[nt][0] * inv0;
        O[gr0 * DD + col + 1] = o[nt][1] * inv0;
        O[(gr0 + 8) * DD + col] = o[nt][2] * inv1;
        O[(gr0 + 8) * DD + col + 1] = o[nt][3] * inv1;
    }
}

extern "C" void kernel_launch(void* const* d_in, const int* in_sizes, int n_in,
                              void* d_out, int out_size)
{
    (void)in_sizes; (void)n_in; (void)out_size;
    const float* x    = (const float*)d_in[0];
    const float* anw  = (const float*)d_in[1];
    const float* anb  = (const float*)d_in[2];
    const float* Wdq  = (const float*)d_in[3];
    const float* qlw  = (const float*)d_in[4];
    const float* qlb  = (const float*)d_in[5];
    const float* Wuq  = (const float*)d_in[6];
    const float* Wdkv = (const float*)d_in[7];
    const float* klw  = (const float*)d_in[8];
    const float* klb  = (const float*)d_in[9];
    const float* Wukv = (const float*)d_in[10];
    const float* Wo   = (const float*)d_in[11];
    const float* fnw  = (const float*)d_in[12];
    const float* fnb  = (const float*)d_in[13];
    const float* W1   = (const float*)d_in[14];
    const float* b1   = (const float*)d_in[15];
    const float* W2   = (const float*)d_in[16];
    const float* b2   = (const float*)d_in[17];

    float* out = (float*)d_out;
    float* ckv = out + (size_t)MMr * DD;

    float *ph, *pcq, *pqraw, *pkvl, *pkvraw, *pq, *pk, *pv, *po, *px2, *pff1, *pwoT, *pwdkvp;
    cudaGetSymbolAddress((void**)&ph, g_h);
    cudaGetSymbolAddress((void**)&pcq, g_cq);
    cudaGetSymbolAddress((void**)&pqraw, g_qraw);
    cudaGetSymbolAddress((void**)&pkvl, g_kvlora);
    cudaGetSymbolAddress((void**)&pkvraw, g_kvraw);
    cudaGetSymbolAddress((void**)&pq, g_q);
    cudaGetSymbolAddress((void**)&pk, g_k);
    cudaGetSymbolAddress((void**)&pv, g_v);
    cudaGetSymbolAddress((void**)&po, g_o);
    cudaGetSymbolAddress((void**)&px2, g_x2);
    cudaGetSymbolAddress((void**)&pff1, g_ff1);
    cudaGetSymbolAddress((void**)&pwoT, g_woT);
    cudaGetSymbolAddress((void**)&pwdkvp, g_wdkvp);

    cudaFuncSetAttribute(gemm_kernel<0>, cudaFuncAttributeMaxDynamicSharedMemorySize, GEMM_SMEM);
    cudaFuncSetAttribute(gemm_kernel<1>, cudaFuncAttributeMaxDynamicSharedMemorySize, GEMM_SMEM);
    cudaFuncSetAttribute(gemm_kernel<2>, cudaFuncAttributeMaxDynamicSharedMemorySize, GEMM_SMEM);
    cudaFuncSetAttribute(attn_kernel, cudaFuncAttributeMaxDynamicSharedMemorySize, ATTN_SMEM);

    dim3 blk(256);
    freqs_kernel<<<1, 32>>>();
    ln_kernel<<<MMr, 256, DD * 4>>>(x, DD, DD, anw, anb, ph, DD, DD);
    transpose_kernel<<<dim3(64, 64), dim3(32, 8)>>>(Wo, pwoT, DD);
    pad_wdkv_kernel<<<DD, 256>>>(Wdkv, pwdkvp);

    // cq_raw = h @ W_dq
    gemm_kernel<0><<<dim3(QPd / BN, MMr / BM), blk, GEMM_SMEM>>>(
        ph, DD, DD, Wdq, QPd, QPd, pcq, QPd, MMr, QPd, DD, nullptr, nullptr, 0);
    // ckv = h @ W_dkv (second output, pre-LN)
    gemm_kernel<0><<<dim3((CKVN + BN - 1) / BN, MMr / BM), blk, GEMM_SMEM>>>(
        ph, DD, DD, pwdkvp, WDKV_PAD, WDKV_PAD, ckv, CKVN, MMr, CKVN, DD, nullptr, nullptr, 0);
    ln_kernel<<<MMr, 256, QPd * 4>>>(pcq, QPd, QPd, qlw, qlb, pcq, QPd, QPd);
    ln_kernel<<<MMr, 256, KVPd * 4>>>(ckv, CKVN, KVPd, klw, klb, pkvl, KVL_PAD, KVL_PAD);
    // Q_raw = cq @ W_uq
    gemm_kernel<0><<<dim3(DD / BN, MMr / BM), blk, GEMM_SMEM>>>(
        pcq, QPd, QPd, Wuq, DD, DD, pqraw, DD, MMr, DD, QPd, nullptr, nullptr, 0);
    // KV_raw = kv_lora @ W_ukv
    gemm_kernel<0><<<dim3(3072 / BN, MMr / BM), blk, GEMM_SMEM>>>(
        pkvl, KVL_PAD, KVL_PAD, Wukv, 3072, 3072, pkvraw, 3072, MMr, 3072, KVPd, nullptr, nullptr, 0);

    rope_q_kernel<<<MMr, 256>>>(pqraw, pq);
    reorder_kv_kernel<<<MMr, 256>>>(pkvraw, ckv, pk, pv);
    attn_kernel<<<dim3(SS / 64, BB * HH), 128, ATTN_SMEM>>>(pq, pk, pv, po);

    // x2 = x + o @ Wo^T
    gemm_kernel<2><<<dim3(DD / BN, MMr / BM), blk, GEMM_SMEM>>>(
        po, DD, DD, pwoT, DD, DD, px2, DD, MMr, DD, DD, nullptr, x, DD);
    ln_kernel<<<MMr, 256, DD * 4>>>(px2, DD, DD, fnw, fnb, ph, DD, DD);
    // ff1 = gelu(h @ W1 + b1)
    gemm_kernel<1><<<dim3(FFd / BN, MMr / BM), blk, GEMM_SMEM>>>(
        ph, DD, DD, W1, FFd, FFd, pff1, FFd, MMr, FFd, DD, b1, nullptr, 0);
    // out = x2 + ff1 @ W2 + b2
    gemm_kernel<2><<<dim3(DD / BN, MMr / BM), blk, GEMM_SMEM>>>(
        pff1, FFd, FFd, W2, DD, DD, out, DD, MMr, DD, FFd, b2, px2, DD);
}

// round 9
// speedup vs baseline: 1.2086x; 1.2086x over previous
#include <cuda_runtime.h>
#include <cuda_bf16.h>
#include <math.h>
#include <stdint.h>

#define BB 2
#define SS 2048
#define DD 2048
#define HH 16
#define QPd 1024
#define KVPd 1365
#define CKVN 1429
#define FFd 8192
#define MMr 4096
#define KVL_PAD 1376
#define WDKV_PAD 1440

__device__ float g_h[(size_t)MMr * DD];
__device__ float g_cq[(size_t)MMr * QPd];
__device__ float g_qraw[(size_t)MMr * DD];
__device__ float g_kvlora[(size_t)MMr * KVL_PAD];
__device__ float g_kvraw[(size_t)MMr * 3072];
__device__ float g_q[(size_t)MMr * DD];
__device__ float g_k[(size_t)MMr * DD];
__device__ float g_v[(size_t)MMr * DD];
__device__ float g_o[(size_t)MMr * DD];
__device__ float g_x2[(size_t)MMr * DD];
__device__ float g_ff1[(size_t)MMr * FFd];
__device__ float g_woT[(size_t)DD * DD];
__device__ float g_wdkvp[(size_t)DD * WDKV_PAD];
__device__ float g_wdqc[(size_t)DD * QPd];
__device__ float g_wuqc[(size_t)QPd * DD];
__device__ float g_wukvc[(size_t)KVPd * 3072];
__device__ float g_w1c[(size_t)DD * FFd];
__device__ float g_w2c[(size_t)FFd * DD];
__device__ float g_freqs[32];

__device__ __forceinline__ uint32_t f2tf(float x) {
    uint32_t u;
    asm("cvt.rna.tf32.f32 %0, %1;" : "=r"(u) : "f"(x));
    return u;
}
// round-to-tf32, keep as float bits (idempotent under mma's internal cvt)
__device__ __forceinline__ float rtf(float x) { return __uint_as_float(f2tf(x)); }

__device__ __forceinline__ void mma_tf32(float* c, const uint32_t* a, uint32_t b0, uint32_t b1) {
    asm volatile(
        "mma.sync.aligned.m16n8k8.row.col.f32.tf32.tf32.f32 "
        "{%0,%1,%2,%3}, {%4,%5,%6,%7}, {%8,%9}, {%0,%1,%2,%3};"
        : "+f"(c[0]), "+f"(c[1]), "+f"(c[2]), "+f"(c[3])
        : "r"(a[0]), "r"(a[1]), "r"(a[2]), "r"(a[3]), "r"(b0), "r"(b1));
}
__device__ __forceinline__ void cp16(float* dst, const float* src, const float* safe, bool p) {
    uint32_t d = (uint32_t)__cvta_generic_to_shared(dst);
    const float* s = p ? src : safe;
    int sz = p ? 16 : 0;
    asm volatile("cp.async.cg.shared.global [%0], [%1], 16, %2;" :: "r"(d), "l"(s), "r"(sz));
}

#define BM 128
#define BN 128
#define BKt 32
#define ASTR 36
#define BSTR 136
#define AS_ELE (BM * ASTR)
#define BS_ELE (BKt * BSTR)
#define GEMM_SMEM (2 * (AS_ELE + BS_ELE) * 4)

// EPI: 0 none, 1 bias+GELU (rounded output -> feeds GEMM), 2 (+bias)+residual (exact)
template <int EPI>
__global__ __launch_bounds__(256) void gemm_kernel(
    const float* __restrict__ A, int lda, int kbuf,
    const float* __restrict__ B, int ldb, int nbuf,
    float* __restrict__ C, int ldc, int M, int N, int K,
    const float* __restrict__ bias, const float* __restrict__ res, int ldres)
{
    extern __shared__ float smemb[];
    float* As = smemb;
    float* Bs = smemb + 2 * AS_ELE;
    const int tid = threadIdx.x, lane = tid & 31, warp = tid >> 5;
    const int wm = warp >> 1, wn = warp & 1;
    const int bm0 = blockIdx.y * BM, bn0 = blockIdx.x * BN;

    float acc[2][8][4];
#pragma unroll
    for (int i = 0; i < 2; i++)
#pragma unroll
        for (int j = 0; j < 8; j++)
#pragma unroll
            for (int c = 0; c < 4; c++) acc[i][j][c] = 0.f;

    const int KT = (K + BKt - 1) / BKt;
    auto load_tiles = [&](int buf, int k0) {
        float* Ab = As + buf * AS_ELE;
        float* Bb = Bs + buf * BS_ELE;
        const int ar = tid >> 3, ac = (tid & 7) * 4;
#pragma unroll
        for (int i = 0; i < 4; i++) {
            int r = i * 32 + ar;
            cp16(Ab + r * ASTR + ac, A + (size_t)(bm0 + r) * lda + k0 + ac, A, (k0 + ac) < kbuf);
        }
        const int br = tid >> 5, bc = (tid & 31) * 4;
#pragma unroll
        for (int i = 0; i < 4; i++) {
            int r = i * 8 + br;
            cp16(Bb + r * BSTR + bc, B + (size_t)(k0 + r) * ldb + bn0 + bc, B,
                 ((k0 + r) < K) && ((bn0 + bc) < nbuf));
        }
        asm volatile("cp.async.commit_group;");
    };

    load_tiles(0, 0);
    int buf = 0;
    for (int kt = 0; kt < KT; kt++) {
        if (kt + 1 < KT) {
            load_tiles(buf ^ 1, (kt + 1) * BKt);
            asm volatile("cp.async.wait_group 1;");
        } else {
            asm volatile("cp.async.wait_group 0;");
        }
        __syncthreads();
        const float* Ab = As + buf * AS_ELE;
        const float* Bb = Bs + buf * BS_ELE;
#pragma unroll
        for (int ks = 0; ks < BKt / 8; ks++) {
            const int kb = ks * 8;
            uint32_t a[2][4];
#pragma unroll
            for (int im = 0; im < 2; im++) {
                const int r = wm * 32 + im * 16 + (lane >> 2);
                const int cc = kb + (lane & 3);
                a[im][0] = __float_as_uint(Ab[r * ASTR + cc]);
                a[im][1] = __float_as_uint(Ab[(r + 8) * ASTR + cc]);
                a[im][2] = __float_as_uint(Ab[r * ASTR + cc + 4]);
                a[im][3] = __float_as_uint(Ab[(r + 8) * ASTR + cc + 4]);
            }
#pragma unroll
            for (int in_ = 0; in_ < 8; in_++) {
                const int c = wn * 64 + in_ * 8 + (lane >> 2);
                uint32_t b0 = __float_as_uint(Bb[(kb + (lane & 3)) * BSTR + c]);
                uint32_t b1 = __float_as_uint(Bb[(kb + (lane & 3) + 4) * BSTR + c]);
#pragma unroll
                for (int im = 0; im < 2; im++) mma_tf32(acc[im][in_], a[im], b0, b1);
            }
        }
        __syncthreads();
        buf ^= 1;
    }
#pragma unroll
    for (int im = 0; im < 2; im++)
#pragma unroll
        for (int in_ = 0; in_ < 8; in_++) {
            const int r0 = bm0 + wm * 32 + im * 16 + (lane >> 2);
            const int c0 = bn0 + wn * 64 + in_ * 8 + 2 * (lane & 3);
#pragma unroll
            for (int cc = 0; cc < 4; cc++) {
                int r = r0 + (cc >> 1) * 8;
                int c = c0 + (cc & 1);
                if (c < N) {
                    float v = acc[im][in_][cc];
                    if (EPI == 1) {
                        v += bias[c];
                        v = 0.5f * v * (1.f + erff(v * 0.7071067811865475f));
                        v = rtf(v);
                    } else if (EPI == 2) {
                        if (bias) v += bias[c];
                        v += res[(size_t)r * ldres + c];
                    }
                    C[(size_t)r * ldc + c] = v;
                }
            }
        }
}

// LN: output feeds GEMM A operands only -> round to tf32 at store
__global__ void ln_kernel(const float* __restrict__ in, int ldin, int cols,
                          const float* __restrict__ w, const float* __restrict__ b,
                          float* __restrict__ out, int ldout, int padto)
{
    extern __shared__ float sbuf[];
    __shared__ float red[8];
    __shared__ float bc[2];
    const int row = blockIdx.x, tid = threadIdx.x, lane = tid & 31, warp = tid >> 5;
    const float* ip = in + (size_t)row * ldin;
    float s = 0.f;
    for (int c = tid; c < cols; c += 256) { float v = ip[c]; sbuf[c] = v; s += v; }
#pragma unroll
    for (int o = 16; o > 0; o >>= 1) s += __shfl_xor_sync(0xffffffffu, s, o);
    if (lane == 0) red[warp] = s;
    __syncthreads();
    if (tid == 0) { float t = 0; for (int i = 0; i < 8; i++) t += red[i]; bc[0] = t / cols; }
    __syncthreads();
    float mean = bc[0], vs = 0.f;
    for (int c = tid; c < cols; c += 256) { float d = sbuf[c] - mean; vs += d * d; }
#pragma unroll
    for (int o = 16; o > 0; o >>= 1) vs += __shfl_xor_sync(0xffffffffu, vs, o);
    if (lane == 0) red[warp] = vs;
    __syncthreads();
    if (tid == 0) { float t = 0; for (int i = 0; i < 8; i++) t += red[i]; bc[1] = rsqrtf(t / cols + 1e-5f); }
    __syncthreads();
    float inv = bc[1];
    float* op = out + (size_t)row * ldout;
    for (int c = tid; c < cols; c += 256) op[c] = rtf((sbuf[c] - mean) * inv * w[c] + b[c]);
    for (int c = cols + tid; c < padto; c += 256) op[c] = 0.f;
}

__global__ void freqs_kernel() {
    int j = threadIdx.x;
    if (j < 32) g_freqs[j] = (float)exp(-(double)j * 0.14391156831212787);
}

__global__ void transpose_kernel(const float* __restrict__ in, float* __restrict__ out, int n) {
    __shared__ float t[32][33];
    int x = blockIdx.x * 32 + threadIdx.x;
    int y = blockIdx.y * 32 + threadIdx.y;
#pragma unroll
    for (int i = 0; i < 32; i += 8) t[threadIdx.y + i][threadIdx.x] = in[(size_t)(y + i) * n + x];
    __syncthreads();
    int ox = blockIdx.y * 32 + threadIdx.x;
    int oy = blockIdx.x * 32 + threadIdx.y;
#pragma unroll
    for (int i = 0; i < 32; i += 8) out[(size_t)(oy + i) * n + ox] = rtf(t[threadIdx.x][threadIdx.y + i]);
}

__global__ void pad_wdkv_kernel(const float* __restrict__ in, float* __restrict__ out) {
    int r = blockIdx.x;
    for (int c = threadIdx.x; c < WDKV_PAD; c += 256)
        out[(size_t)r * WDKV_PAD + c] = (c < CKVN) ? rtf(in[(size_t)r * CKVN + c]) : 0.f;
}

// one-shot tf32 rounding of the 5 dense weights
#define NW0 ((size_t)DD * QPd)
#define NW1 ((size_t)QPd * DD)
#define NW2 ((size_t)KVPd * 3072)
#define NW3 ((size_t)DD * FFd)
#define NW4 ((size_t)FFd * DD)
__global__ void cvtw_kernel(const float* __restrict__ s0, float* __restrict__ d0,
                            const float* __restrict__ s1, float* __restrict__ d1,
                            const float* __restrict__ s2, float* __restrict__ d2,
                            const float* __restrict__ s3, float* __restrict__ d3,
                            const float* __restrict__ s4, float* __restrict__ d4)
{
    const size_t total = NW0 + NW1 + NW2 + NW3 + NW4;
    for (size_t i = (size_t)blockIdx.x * blockDim.x + threadIdx.x; i < total;
         i += (size_t)gridDim.x * blockDim.x) {
        size_t j = i;
        if (j < NW0) { d0[j] = rtf(s0[j]); continue; }
        j -= NW0;
        if (j < NW1) { d1[j] = rtf(s1[j]); continue; }
        j -= NW1;
        if (j < NW2) { d2[j] = rtf(s2[j]); continue; }
        j -= NW2;
        if (j < NW3) { d3[j] = rtf(s3[j]); continue; }
        j -= NW3;
        d4[j] = rtf(s4[j]);
    }
}

__global__ void rope_q_kernel(const float* __restrict__ qraw, float* __restrict__ qout) {
    int bs = blockIdx.x;
    int s = bs & (SS - 1), b = bs >> 11;
    for (int i = threadIdx.x; i < DD; i += 256) {
        int hh = i >> 7, d = i & 127;
        const float* src = qraw + (size_t)bs * DD + hh * 128;
        float v;
        if (d < 64) {
            v = src[d];
        } else {
            int dd = d - 64;
            int j = dd & 31;
            float t = (float)s * g_freqs[j];
            float x = src[64 + dd];
            float rx = (dd < 32) ? -src[64 + dd + 32] : src[64 + dd - 32];
            v = x * cosf(t) + rx * sinf(t);
        }
        qout[(((size_t)b * HH + hh) * SS + s) * 128 + d] = rtf(v);
    }
}

__global__ void reorder_kv_kernel(const float* __restrict__ kvraw, const float* __restrict__ ckv,
                                  float* __restrict__ kout, float* __restrict__ vout) {
    __shared__ float kr[64];
    int bs = blockIdx.x;
    int s = bs & (SS - 1), b = bs >> 11;
    int tid = threadIdx.x;
    if (tid < 64) {
        int dd = tid, j = dd & 31;
        float t = (float)s * g_freqs[j];
        const float* src = ckv + (size_t)bs * CKVN + KVPd;
        float x = src[dd];
        float rx = (dd < 32) ? -src[dd + 32] : src[dd - 32];
        kr[dd] = rtf(x * cosf(t) + rx * sinf(t));
    }
    __syncthreads();
    for (int i = tid; i < HH * 192; i += 256) {
        int hh = i / 192, d = i % 192;
        float v = rtf(kvraw[(size_t)bs * 3072 + i]);
        size_t base = (((size_t)b * HH + hh) * SS + s) * 128;
        if (d < 64) kout[base + d] = v;
        else vout[base + (d - 64)] = v;
    }
    for (int i = tid; i < HH * 64; i += 256) {
        int hh = i >> 6, dd = i & 63;
        kout[(((size_t)b * HH + hh) * SS + s) * 128 + 64 + dd] = kr[dd];
    }
}

#define QSTR 132
#define VSTR 136
#define ATTN_SMEM ((64 * QSTR + 32 * QSTR + 32 * VSTR + 4 * 16 * 36) * 4)

__global__ __launch_bounds__(128) void attn_kernel(
    const float* __restrict__ Q, const float* __restrict__ Kk,
    const float* __restrict__ V, float* __restrict__ O)
{
    extern __shared__ float smema[];
    float* qs = smema;                 // [64][132]
    float* ks = qs + 64 * QSTR;        // [32][132]
    float* vs = ks + 32 * QSTR;        // [32][136]
    float* ps = vs + 32 * VSTR;        // [4][16][36]
    const int qb = blockIdx.x, bh = blockIdx.y;
    const int b = bh >> 4, h = bh & 15;
    const int tid = threadIdx.x, lane = tid & 31, w = tid >> 5;
    const int g = lane >> 2, t = lane & 3;

    const float* Qb = Q + ((size_t)bh * SS + qb * 64) * 128;
    const float* Kb = Kk + (size_t)bh * SS * 128;
    const float* Vb = V + (size_t)bh * SS * 128;

    for (int i = tid; i < 64 * 32; i += 128) {
        int r = i >> 5, c4 = (i & 31) * 4;
        *(float4*)(qs + r * QSTR + c4) = *(const float4*)(Qb + r * 128 + c4);
    }
    __syncthreads();

    float m_[2] = {-1e30f, -1e30f};
    float l_[2] = {0.f, 0.f};
    float o[16][4];
#pragma unroll
    for (int i = 0; i < 16; i++)
#pragma unroll
        for (int c = 0; c < 4; c++) o[i][c] = 0.f;

    const int nkt = qb * 2 + 2;
    const float scale = 0.08838834764831845f;
    float* pw = ps + w * 16 * 36;

    for (int kt = 0; kt < nkt; kt++) {
        for (int i = tid; i < 32 * 32; i += 128) {
            int r = i >> 5, c4 = (i & 31) * 4;
            *(float4*)(ks + r * QSTR + c4) = *(const float4*)(Kb + ((size_t)kt * 32 + r) * 128 + c4);
            *(float4*)(vs + r * VSTR + c4) = *(const float4*)(Vb + ((size_t)kt * 32 + r) * 128 + c4);
        }
        __syncthreads();

        float s[4][4];
#pragma unroll
        for (int nt = 0; nt < 4; nt++)
#pragma unroll
            for (int c = 0; c < 4; c++) s[nt][c] = 0.f;

#pragma unroll
        for (int k8 = 0; k8 < 16; k8++) {
            const int kb2 = k8 * 8;
            uint32_t a[4];
            const int rb = w * 16;
            a[0] = __float_as_uint(qs[(rb + g) * QSTR + kb2 + t]);
            a[1] = __float_as_uint(qs[(rb + g + 8) * QSTR + kb2 + t]);
            a[2] = __float_as_uint(qs[(rb + g) * QSTR + kb2 + t + 4]);
            a[3] = __float_as_uint(qs[(rb + g + 8) * QSTR + kb2 + t + 4]);
#pragma unroll
            for (int nt = 0; nt < 4; nt++) {
                uint32_t b0 = __float_as_uint(ks[(nt * 8 + g) * QSTR + kb2 + t]);
                uint32_t b1 = __float_as_uint(ks[(nt * 8 + g) * QSTR + kb2 + t + 4]);
                mma_tf32(s[nt], a, b0, b1);
            }
        }

        const int qrow0 = qb * 64 + w * 16 + g;
        const int qrow1 = qrow0 + 8;
#pragma unroll
        for (int nt = 0; nt < 4; nt++)
#pragma unroll
            for (int c = 0; c < 4; c++) {
                int row = (c < 2) ? qrow0 : qrow1;
                int kidx = kt * 32 + nt * 8 + 2 * t + (c & 1);
                float v = s[nt][c] * scale;
                if (kidx > row) v = -1e30f;
                s[nt][c] = v;
            }

        float mx0 = -1e30f, mx1 = -1e30f;
#pragma unroll
        for (int nt = 0; nt < 4; nt++) {
            mx0 = fmaxf(mx0, fmaxf(s[nt][0], s[nt][1]));
            mx1 = fmaxf(mx1, fmaxf(s[nt][2], s[nt][3]));
        }
#pragma unroll
        for (int off = 1; off < 4; off <<= 1) {
            mx0 = fmaxf(mx0, __shfl_xor_sync(0xffffffffu, mx0, off));
            mx1 = fmaxf(mx1, __shfl_xor_sync(0xffffffffu, mx1, off));
        }
        float mn0 = fmaxf(m_[0], mx0), mn1 = fmaxf(m_[1], mx1);
        float al0 = expf(m_[0] - mn0), al1 = expf(m_[1] - mn1);
        float rs0 = 0.f, rs1 = 0.f;
#pragma unroll
        for (int nt = 0; nt < 4; nt++) {
            s[nt][0] = expf(s[nt][0] - mn0);
            s[nt][1] = expf(s[nt][1] - mn0);
            s[nt][2] = expf(s[nt][2] - mn1);
            s[nt][3] = expf(s[nt][3] - mn1);
            rs0 += s[nt][0] + s[nt][1];
            rs1 += s[nt][2] + s[nt][3];
        }
#pragma unroll
        for (int off = 1; off < 4; off <<= 1) {
            rs0 += __shfl_xor_sync(0xffffffffu, rs0, off);
            rs1 += __shfl_xor_sync(0xffffffffu, rs1, off);
        }
        l_[0] = l_[0] * al0 + rs0;
        l_[1] = l_[1] * al1 + rs1;
        m_[0] = mn0; m_[1] = mn1;
#pragma unroll
        for (int nt = 0; nt < 16; nt++) {
            o[nt][0] *= al0; o[nt][1] *= al0;
            o[nt][2] *= al1; o[nt][3] *= al1;
        }

#pragma unroll
        for (int nt = 0; nt < 4; nt++) {
            pw[g * 36 + nt * 8 + 2 * t] = rtf(s[nt][0]);
            pw[g * 36 + nt * 8 + 2 * t + 1] = rtf(s[nt][1]);
            pw[(g + 8) * 36 + nt * 8 + 2 * t] = rtf(s[nt][2]);
            pw[(g + 8) * 36 + nt * 8 + 2 * t + 1] = rtf(s[nt][3]);
        }
        __syncwarp();

#pragma unroll
        for (int k8 = 0; k8 < 4; k8++) {
            const int kb2 = k8 * 8;
            uint32_t a[4];
            a[0] = __float_as_uint(pw[g * 36 + kb2 + t]);
            a[1] = __float_as_uint(pw[(g + 8) * 36 + kb2 + t]);
            a[2] = __float_as_uint(pw[g * 36 + kb2 + t + 4]);
            a[3] = __float_as_uint(pw[(g + 8) * 36 + kb2 + t + 4]);
#pragma unroll
            for (int nt = 0; nt < 16; nt++) {
                uint32_t b0 = __float_as_uint(vs[(kb2 + t) * VSTR + nt * 8 + g]);
                uint32_t b1 = __float_as_uint(vs[(kb2 + t + 4) * VSTR + nt * 8 + g]);
                mma_tf32(o[nt], a, b0, b1);
            }
        }
        __syncwarp();
        __syncthreads();
    }

    float inv0 = 1.f / l_[0], inv1 = 1.f / l_[1];
    const size_t gr0 = (size_t)b * SS + qb * 64 + w * 16 + g;
#pragma unroll
    for (int nt = 0; nt < 16; nt++) {
        int col = h * 128 + nt * 8 + 2 * t;
        O[gr0 * DD + col] = rtf(o[nt][0] * inv0);
        O[gr0 * DD + col + 1] = rtf(o[nt][1] * inv0);
        O[(gr0 + 8) * DD + col] = rtf(o[nt][2] * inv1);
        O[(gr0 + 8) * DD + col + 1] = rtf(o[nt][3] * inv1);
    }
}

extern "C" void kernel_launch(void* const* d_in, const int* in_sizes, int n_in,
                              void* d_out, int out_size)
{
    (void)in_sizes; (void)n_in; (void)out_size;
    const float* x    = (const float*)d_in[0];
    const float* anw  = (const float*)d_in[1];
    const float* anb  = (const float*)d_in[2];
    const float* Wdq  = (const float*)d_in[3];
    const float* qlw  = (const float*)d_in[4];
    const float* qlb  = (const float*)d_in[5];
    const float* Wuq  = (const float*)d_in[6];
    const float* Wdkv = (const float*)d_in[7];
    const float* klw  = (const float*)d_in[8];
    const float* klb  = (const float*)d_in[9];
    const float* Wukv = (const float*)d_in[10];
    const float* Wo   = (const float*)d_in[11];
    const float* fnw  = (const float*)d_in[12];
    const float* fnb  = (const float*)d_in[13];
    const float* W1   = (const float*)d_in[14];
    const float* b1   = (const float*)d_in[15];
    const float* W2   = (const float*)d_in[16];
    const float* b2   = (const float*)d_in[17];

    float* out = (float*)d_out;
    float* ckv = out + (size_t)MMr * DD;

    float *ph, *pcq, *pqraw, *pkvl, *pkvraw, *pq, *pk, *pv, *po, *px2, *pff1, *pwoT, *pwdkvp;
    float *pwdqc, *pwuqc, *pwukvc, *pw1c, *pw2c;
    cudaGetSymbolAddress((void**)&ph, g_h);
    cudaGetSymbolAddress((void**)&pcq, g_cq);
    cudaGetSymbolAddress((void**)&pqraw, g_qraw);
    cudaGetSymbolAddress((void**)&pkvl, g_kvlora);
    cudaGetSymbolAddress((void**)&pkvraw, g_kvraw);
    cudaGetSymbolAddress((void**)&pq, g_q);
    cudaGetSymbolAddress((void**)&pk, g_k);
    cudaGetSymbolAddress((void**)&pv, g_v);
    cudaGetSymbolAddress((void**)&po, g_o);
    cudaGetSymbolAddress((void**)&px2, g_x2);
    cudaGetSymbolAddress((void**)&pff1, g_ff1);
    cudaGetSymbolAddress((void**)&pwoT, g_woT);
    cudaGetSymbolAddress((void**)&pwdkvp, g_wdkvp);
    cudaGetSymbolAddress((void**)&pwdqc, g_wdqc);
    cudaGetSymbolAddress((void**)&pwuqc, g_wuqc);
    cudaGetSymbolAddress((void**)&pwukvc, g_wukvc);
    cudaGetSymbolAddress((void**)&pw1c, g_w1c);
    cudaGetSymbolAddress((void**)&pw2c, g_w2c);

    cudaFuncSetAttribute(gemm_kernel<0>, cudaFuncAttributeMaxDynamicSharedMemorySize, GEMM_SMEM);
    cudaFuncSetAttribute(gemm_kernel<1>, cudaFuncAttributeMaxDynamicSharedMemorySize, GEMM_SMEM);
    cudaFuncSetAttribute(gemm_kernel<2>, cudaFuncAttributeMaxDynamicSharedMemorySize, GEMM_SMEM);
    cudaFuncSetAttribute(attn_kernel, cudaFuncAttributeMaxDynamicSharedMemorySize, ATTN_SMEM);

    dim3 blk(256);
    // launch order chosen so ncu (-s 5 -c 1) captures launch #5 = first big GEMM
    freqs_kernel<<<1, 32>>>();                                            // 0
    ln_kernel<<<MMr, 256, DD * 4>>>(x, DD, DD, anw, anb, ph, DD, DD);     // 1
    transpose_kernel<<<dim3(64, 64), dim3(32, 8)>>>(Wo, pwoT, DD);        // 2
    pad_wdkv_kernel<<<DD, 256>>>(Wdkv, pwdkvp);                           // 3
    cvtw_kernel<<<4096, 256>>>(Wdq, pwdqc, Wuq, pwuqc, Wukv, pwukvc,
                               W1, pw1c, W2, pw2c);                       // 4

    // 5: cq_raw = h @ W_dq   <-- profiled launch
    gemm_kernel<0><<<dim3(QPd / BN, MMr / BM), blk, GEMM_SMEM>>>(
        ph, DD, DD, pwdqc, QPd, QPd, pcq, QPd, MMr, QPd, DD, nullptr, nullptr, 0);
    // ckv = h @ W_dkv (second output, pre-LN, exact fp32 epilogue)
    gemm_kernel<0><<<dim3((CKVN + BN - 1) / BN, MMr / BM), blk, GEMM_SMEM>>>(
        ph, DD, DD, pwdkvp, WDKV_PAD, WDKV_PAD, ckv, CKVN, MMr, CKVN, DD, nullptr, nullptr, 0);
    ln_kernel<<<MMr, 256, QPd * 4>>>(pcq, QPd, QPd, qlw, qlb, pcq, QPd, QPd);
    ln_kernel<<<MMr, 256, KVPd * 4>>>(ckv, CKVN, KVPd, klw, klb, pkvl, KVL_PAD, KVL_PAD);
    // Q_raw = cq @ W_uq
    gemm_kernel<0><<<dim3(DD / BN, MMr / BM), blk, GEMM_SMEM>>>(
        pcq, QPd, QPd, pwuqc, DD, DD, pqraw, DD, MMr, DD, QPd, nullptr, nullptr, 0);
    // KV_raw = kv_lora @ W_ukv
    gemm_kernel<0><<<dim3(3072 / BN, MMr / BM), blk, GEMM_SMEM>>>(
        pkvl, KVL_PAD, KVL_PAD, pwukvc, 3072, 3072, pkvraw, 3072, MMr, 3072, KVPd, nullptr, nullptr, 0);

    rope_q_kernel<<<MMr, 256>>>(pqraw, pq);
    reorder_kv_kernel<<<MMr, 256>>>(pkvraw, ckv, pk, pv);
    attn_kernel<<<dim3(SS / 64, BB * HH), 128, ATTN_SMEM>>>(pq, pk, pv, po);

    // x2 = x + o @ Wo^T  (exact fp32)
    gemm_kernel<2><<<dim3(DD / BN, MMr / BM), blk, GEMM_SMEM>>>(
        po, DD, DD, pwoT, DD, DD, px2, DD, MMr, DD, DD, nullptr, x, DD);
    ln_kernel<<<MMr, 256, DD * 4>>>(px2, DD, DD, fnw, fnb, ph, DD, DD);
    // ff1 = round_tf32(gelu(h @ W1 + b1))
    gemm_kernel<1><<<dim3(FFd / BN, MMr / BM), blk, GEMM_SMEM>>>(
        ph, DD, DD, pw1c, FFd, FFd, pff1, FFd, MMr, FFd, DD, b1, nullptr, 0);
    // out = x2 + ff1 @ W2 + b2  (exact fp32)
    gemm_kernel<2><<<dim3(DD / BN, MMr / BM), blk, GEMM_SMEM>>>(
        pff1, FFd, FFd, pw2c, DD, DD, out, DD, MMr, DD, FFd, b2, px2, DD);
}